// round 10
// baseline (speedup 1.0000x reference)
#include <cuda_runtime.h>
#include <cuda_bf16.h>
#include <math.h>
#include <stdint.h>

#define TOK 1024
#define HID 2048
#define IMD 768
#define GUD 1536
#define NE  8
#define NBLK 148
#define NTH 512
#define NT (NBLK*NTH)

// ---- per-stage smem: A 128x64 bf16 (h+l) + B 256x64 bf16 (h+l), 128B swizzled rows
#define SA_H 0
#define SA_L 16384
#define SB_H 32768
#define SB_L 65536
#define STAGE_BYTES 98304
#define NSTG 2
#define SMEM_BYTES (NSTG*STAGE_BYTES)   // 196608

// ---------------- scratch (device globals) ----------------
__device__ __align__(16) int   g_cnt[NE];
__device__ __align__(16) int   g_list[NE*TOK];
__device__ __align__(16) float g_topw[2*TOK];
__device__ __align__(16) float g_gu[2*TOK*GUD];
__device__ __align__(16) float g_o2[2*TOK*HID];
__device__ __align__(16) __nv_bfloat16 g_xh [TOK*HID],     g_xl [TOK*HID];
__device__ __align__(16) __nv_bfloat16 g_wuh[NE*GUD*HID],  g_wul[NE*GUD*HID];
__device__ __align__(16) __nv_bfloat16 g_wdh[NE*HID*IMD],  g_wdl[NE*HID*IMD];
__device__ __align__(16) __nv_bfloat16 g_hbh[2*TOK*IMD],   g_hbl[2*TOK*IMD];
__device__ unsigned          g_bcnt   = 0;
__device__ volatile unsigned g_bsense = 0;

// ---------------- helpers ----------------
__device__ __forceinline__ uint32_t smem_u32(const void* p) {
    uint32_t a;
    asm("{ .reg .u64 t; cvta.to.shared.u64 t, %1; cvt.u32.u64 %0, t; }" : "=r"(a) : "l"(p));
    return a;
}
__device__ __forceinline__ void cp16(uint32_t dst, const void* src) {
    asm volatile("cp.async.cg.shared.global [%0], [%1], 16;" :: "r"(dst), "l"(src) : "memory");
}
__device__ __forceinline__ void cp16p(uint32_t dst, const void* src, int full) {
    asm volatile("cp.async.cg.shared.global [%0], [%1], 16, %2;"
                 :: "r"(dst), "l"(src), "r"(full ? 16 : 0) : "memory");
}
#define CP_COMMIT() asm volatile("cp.async.commit_group;" ::: "memory")
#define CP_WAIT(n)  asm volatile("cp.async.wait_group %0;" :: "n"(n) : "memory")

__device__ __forceinline__ void ldsm_x4(uint32_t r[4], uint32_t addr) {
    asm volatile("ldmatrix.sync.aligned.m8n8.x4.shared.b16 {%0,%1,%2,%3}, [%4];"
        : "=r"(r[0]), "=r"(r[1]), "=r"(r[2]), "=r"(r[3]) : "r"(addr));
}
__device__ __forceinline__ void mma_bf16(float c[4], const uint32_t a[4], const uint32_t b[2]) {
    asm volatile("mma.sync.aligned.m16n8k16.row.col.f32.bf16.bf16.f32 "
        "{%0,%1,%2,%3}, {%4,%5,%6,%7}, {%8,%9}, {%0,%1,%2,%3};"
        : "+f"(c[0]), "+f"(c[1]), "+f"(c[2]), "+f"(c[3])
        : "r"(a[0]), "r"(a[1]), "r"(a[2]), "r"(a[3]), "r"(b[0]), "r"(b[1]));
}
__device__ __forceinline__ void split4(float4 v, uint2& hi, uint2& lo) {
    __nv_bfloat16 h0 = __float2bfloat16(v.x), h1 = __float2bfloat16(v.y);
    __nv_bfloat16 h2 = __float2bfloat16(v.z), h3 = __float2bfloat16(v.w);
    __nv_bfloat16 l0 = __float2bfloat16(v.x - __bfloat162float(h0));
    __nv_bfloat16 l1 = __float2bfloat16(v.y - __bfloat162float(h1));
    __nv_bfloat16 l2 = __float2bfloat16(v.z - __bfloat162float(h2));
    __nv_bfloat16 l3 = __float2bfloat16(v.w - __bfloat162float(h3));
    hi.x = (uint32_t)__bfloat16_as_ushort(h0) | ((uint32_t)__bfloat16_as_ushort(h1) << 16);
    hi.y = (uint32_t)__bfloat16_as_ushort(h2) | ((uint32_t)__bfloat16_as_ushort(h3) << 16);
    lo.x = (uint32_t)__bfloat16_as_ushort(l0) | ((uint32_t)__bfloat16_as_ushort(l1) << 16);
    lo.y = (uint32_t)__bfloat16_as_ushort(l2) | ((uint32_t)__bfloat16_as_ushort(l3) << 16);
}
__device__ __forceinline__ void gbar(unsigned& ls) {
    __syncthreads();
    if (threadIdx.x == 0) {
        unsigned target = ls + 1u;
        __threadfence();
        unsigned old = atomicAdd(&g_bcnt, 1u);
        if (old == NBLK - 1u) { g_bcnt = 0u; __threadfence(); g_bsense = target; }
        else { while (g_bsense != target) __nanosleep(128); }
        __threadfence();
    }
    ls += 1u;
    __syncthreads();
}
__device__ __forceinline__ float wsum(float v) {
#pragma unroll
    for (int o = 16; o; o >>= 1) v += __shfl_xor_sync(0xffffffffu, v, o);
    return v;
}

// ------------- 128x256xK warp-MMA tile (16 warps of 32x64), 2-stage cp.async -------------
template<int KD, bool SECOND>
__device__ __forceinline__ void mma_tile(
    const __nv_bfloat16* __restrict__ Ah, const __nv_bfloat16* __restrict__ Al,
    const __nv_bfloat16* __restrict__ Bh, const __nv_bfloat16* __restrict__ Bl,
    int e, int m0, int n0, int ne, char* sm, uint32_t sb)
{
    const int tid = threadIdx.x;
    const int wid = tid >> 5, lane = tid & 31;

    // ---- A load mapping: 128 rows, thread = (row=tid>>2, 2 chunks of 16B) ----
    const int arow = tid >> 2;
    const int acq  = (tid & 3) * 2;
    const int a_ok = (m0 + arow < ne);
    const uint4 *agh, *agl;
    {
        int pair = a_ok ? g_list[e*TOK + m0 + arow] : 0;
        size_t ar = (size_t)(SECOND ? pair : (pair >> 1)) * KD;
        agh = (const uint4*)(Ah + ar);
        agl = (const uint4*)(Al + ar);
    }
    uint32_t stsA[2];
#pragma unroll
    for (int j = 0; j < 2; j++) {
        int ch = acq + j;
        stsA[j] = (uint32_t)(arow * 128 + ((ch ^ (arow & 7)) << 4));
    }

    // ---- B load mapping: 256 rows, thread = (row=tid>>1, 4 chunks of 16B) ----
    const int brow = tid >> 1;
    const int bcq  = (tid & 1) * 4;
    const uint4* bgh = (const uint4*)(Bh + (size_t)(n0 + brow) * KD);
    const uint4* bgl = (const uint4*)(Bl + (size_t)(n0 + brow) * KD);
    uint32_t stsB[4];
#pragma unroll
    for (int j = 0; j < 4; j++) {
        int ch = bcq + j;
        stsB[j] = (uint32_t)(brow * 128 + ((ch ^ (brow & 7)) << 4));
    }

    const int KBN = KD / 64;
    auto issue = [&](int kb, int stg) {
        uint32_t base = sb + (uint32_t)stg * STAGE_BYTES;
#pragma unroll
        for (int j = 0; j < 2; j++) {
            int ch = acq + j;
            cp16p(base + SA_H + stsA[j], agh + kb*8 + ch, a_ok);
            cp16p(base + SA_L + stsA[j], agl + kb*8 + ch, a_ok);
        }
#pragma unroll
        for (int j = 0; j < 4; j++) {
            int ch = bcq + j;
            cp16(base + SB_H + stsB[j], bgh + kb*8 + ch);
            cp16(base + SB_L + stsB[j], bgl + kb*8 + ch);
        }
        CP_COMMIT();
    };

    // ---- warp tile: 32m x 64n, warp grid 4m x 4n ----
    const int wm = (wid & 3) * 32;
    const int wn = (wid >> 2) * 64;
    const int q  = lane >> 3, r8 = lane & 7;
    const int a_m_base = wm + (q & 1) * 8 + r8;
    const int a_ch_off = (q >> 1);
    const int b_n_base = wn + (q >> 1) * 8 + r8;
    const int b_ch_off = (q & 1);

    float acc[2][8][4];
#pragma unroll
    for (int i = 0; i < 2; i++)
#pragma unroll
        for (int j = 0; j < 8; j++)
#pragma unroll
            for (int c = 0; c < 4; c++) acc[i][j][c] = 0.f;

    issue(0, 0);

    for (int kb = 0; kb < KBN; kb++) {
        const int stg = kb & 1;
        if (kb + 1 < KBN) issue(kb + 1, stg ^ 1);
        if (kb + 1 < KBN) { CP_WAIT(1); } else { CP_WAIT(0); }
        __syncthreads();

        const uint32_t base = sb + (uint32_t)stg * STAGE_BYTES;
        const uint32_t saH = base + SA_H, saL = base + SA_L;
        const uint32_t sbH = base + SB_H, sbL = base + SB_L;

#pragma unroll
        for (int ks = 0; ks < 4; ks++) {
            uint32_t ahf[2][4], alf[2][4];
#pragma unroll
            for (int mi = 0; mi < 2; mi++) {
                int m_ld = a_m_base + mi * 16;
                uint32_t off = (uint32_t)(m_ld * 128 + (((ks*2 + a_ch_off) ^ (m_ld & 7)) << 4));
                ldsm_x4(ahf[mi], saH + off);
                ldsm_x4(alf[mi], saL + off);
            }
#pragma unroll
            for (int nb = 0; nb < 4; nb++) {
                int n_ld = b_n_base + nb * 16;
                uint32_t off = (uint32_t)(n_ld * 128 + (((ks*2 + b_ch_off) ^ (n_ld & 7)) << 4));
                uint32_t bhf[4], blf[4];
                ldsm_x4(bhf, sbH + off);
                ldsm_x4(blf, sbL + off);
#pragma unroll
                for (int mi = 0; mi < 2; mi++) {
#pragma unroll
                    for (int h = 0; h < 2; h++) {
                        float* c = acc[mi][nb*2 + h];
                        mma_bf16(c, ahf[mi], &bhf[2*h]);
                        mma_bf16(c, ahf[mi], &blf[2*h]);
                        mma_bf16(c, alf[mi], &bhf[2*h]);
                    }
                }
            }
        }
        __syncthreads();   // all warps done reading stage stg before refill
    }

    // ---- epilogue ----
    const int g  = lane >> 2, t4 = lane & 3;
#pragma unroll
    for (int mi = 0; mi < 2; mi++) {
        int mr0 = m0 + wm + mi*16 + g;
        int mr1 = mr0 + 8;
        float* row0 = nullptr; float* row1 = nullptr;
        if (mr0 < ne) {
            int p = g_list[e*TOK + mr0];
            row0 = SECOND ? (g_o2 + (size_t)p * HID) : (g_gu + (size_t)p * GUD);
        }
        if (mr1 < ne) {
            int p = g_list[e*TOK + mr1];
            row1 = SECOND ? (g_o2 + (size_t)p * HID) : (g_gu + (size_t)p * GUD);
        }
#pragma unroll
        for (int nj = 0; nj < 8; nj++) {
            int n = n0 + wn + nj*8 + t4*2;
            if (row0) *(float2*)(row0 + n) = make_float2(acc[mi][nj][0], acc[mi][nj][1]);
            if (row1) *(float2*)(row1 + n) = make_float2(acc[mi][nj][2], acc[mi][nj][3]);
        }
    }
    __syncthreads();
}

// ---------------- persistent fused MoE kernel ----------------
__global__ void __launch_bounds__(NTH) k_moe(
    const float* __restrict__ x,   const float* __restrict__ gw,
    const float* __restrict__ wgu, const float* __restrict__ wd,
    float* __restrict__ out)
{
    extern __shared__ char sm[];
    const uint32_t sb = smem_u32(sm);
    const int tid  = threadIdx.x;
    const int wid  = tid >> 5;
    const int lane = tid & 31;
    const int bid  = blockIdx.x;
    const int gtid = bid * NTH + tid;
    unsigned ls = g_bsense;

    // ---- P0: zero counters + split inputs/weights to bf16 hi/lo ----
    if (bid == 0 && tid < NE) g_cnt[tid] = 0;
    {
        uint2 hi, lo;
        for (long i = gtid; i < (long)TOK*HID/4; i += NT) {
            split4(((const float4*)x)[i], hi, lo);
            ((uint2*)g_xh)[i] = hi; ((uint2*)g_xl)[i] = lo;
        }
        for (long i = gtid; i < (long)NE*GUD*HID/4; i += NT) {
            split4(((const float4*)wgu)[i], hi, lo);
            ((uint2*)g_wuh)[i] = hi; ((uint2*)g_wul)[i] = lo;
        }
        for (long i = gtid; i < (long)NE*HID*IMD/4; i += NT) {
            split4(((const float4*)wd)[i], hi, lo);
            ((uint2*)g_wdh)[i] = hi; ((uint2*)g_wdl)[i] = lo;
        }
    }
    gbar(ls);

    // ---- P1: router (one warp per token) ----
    {
        int t = bid * 16 + wid;
        if (t < TOK) {
            const float* xr = x + (size_t)t * HID;
            float acc[NE];
#pragma unroll
            for (int e2 = 0; e2 < NE; e2++) acc[e2] = 0.f;
            for (int j = lane; j < HID; j += 32) {
                float xv = xr[j];
#pragma unroll
                for (int e2 = 0; e2 < NE; e2++) acc[e2] += xv * gw[e2*HID + j];
            }
#pragma unroll
            for (int e2 = 0; e2 < NE; e2++) acc[e2] = wsum(acc[e2]);
            if (lane == 0) {
                int i1 = 0; float v1 = acc[0];
#pragma unroll
                for (int e2 = 1; e2 < NE; e2++) if (acc[e2] > v1) { v1 = acc[e2]; i1 = e2; }
                int i2 = (i1 == 0) ? 1 : 0; float v2 = acc[i2];
#pragma unroll
                for (int e2 = 0; e2 < NE; e2++) if (e2 != i1 && acc[e2] > v2) { v2 = acc[e2]; i2 = e2; }
                float r  = expf(v2 - v1);          // full-E softmax + top-2 renorm
                float w1 = 1.f / (1.f + r);        // == 2-way softmax over {v1,v2}
                g_topw[2*t+0] = w1;
                g_topw[2*t+1] = r * w1;
                int p1 = atomicAdd(&g_cnt[i1], 1); g_list[i1*TOK + p1] = 2*t + 0;
                int p2 = atomicAdd(&g_cnt[i2], 1); g_list[i2*TOK + p2] = 2*t + 1;
            }
        }
    }
    gbar(ls);

    // ---- P2: GEMM1  x @ Wgu^T -> g_gu  (K=2048, N=1536: 6 n-tiles of 256) ----
    for (int job = bid; job < NE*8*6; job += NBLK) {
        int e  = job / 48;
        int mt = (job % 48) / 6;
        int nt = job % 6;
        int ne = g_cnt[e];
        if (mt * 128 >= ne) continue;
        mma_tile<HID, false>(g_xh, g_xl,
                             g_wuh + (size_t)e*GUD*HID, g_wul + (size_t)e*GUD*HID,
                             e, mt*128, nt*256, ne, sm, sb);
    }
    gbar(ls);

    // ---- P3: act h = silu(g)*u -> bf16 hi/lo ----
    {
        const int n4 = 2*TOK*IMD/4;
        for (int i = gtid; i < n4; i += NT) {
            int p  = i / (IMD/4);
            int j4 = i - p * (IMD/4);
            float4 g4 = *(const float4*)(g_gu + (size_t)p*GUD + 4*j4);
            float4 u4 = *(const float4*)(g_gu + (size_t)p*GUD + IMD + 4*j4);
            float4 h4;
            h4.x = (g4.x / (1.f + expf(-g4.x))) * u4.x;
            h4.y = (g4.y / (1.f + expf(-g4.y))) * u4.y;
            h4.z = (g4.z / (1.f + expf(-g4.z))) * u4.z;
            h4.w = (g4.w / (1.f + expf(-g4.w))) * u4.w;
            uint2 hi, lo;
            split4(h4, hi, lo);
            ((uint2*)g_hbh)[i] = hi; ((uint2*)g_hbl)[i] = lo;
        }
    }
    gbar(ls);

    // ---- P4: GEMM2  h @ Wd^T -> g_o2  (K=768, N=2048: 8 n-tiles of 256) ----
    for (int job = bid; job < NE*8*8; job += NBLK) {
        int e  = job / 64;
        int mt = (job % 64) / 8;
        int nt = job % 8;
        int ne = g_cnt[e];
        if (mt * 128 >= ne) continue;
        mma_tile<IMD, true>(g_hbh, g_hbl,
                            g_wdh + (size_t)e*HID*IMD, g_wdl + (size_t)e*HID*IMD,
                            e, mt*128, nt*256, ne, sm, sb);
    }
    gbar(ls);

    // ---- P5: combine out[t] = w1*y[2t] + w2*y[2t+1] ----
    {
        const int n4 = TOK*HID/4;
        for (int i = gtid; i < n4; i += NT) {
            int t  = i / (HID/4);
            int j4 = i - t * (HID/4);
            float w1 = g_topw[2*t+0], w2 = g_topw[2*t+1];
            float4 y1 = ((const float4*)g_o2)[(size_t)(2*t  )*(HID/4) + j4];
            float4 y2 = ((const float4*)g_o2)[(size_t)(2*t+1)*(HID/4) + j4];
            float4 o;
            o.x = w1*y1.x + w2*y2.x;
            o.y = w1*y1.y + w2*y2.y;
            o.z = w1*y1.z + w2*y2.z;
            o.w = w1*y1.w + w2*y2.w;
            ((float4*)out)[i] = o;
        }
    }
}

// ---------------- launch ----------------
extern "C" void kernel_launch(void* const* d_in, const int* in_sizes, int n_in,
                              void* d_out, int out_size) {
    const long EX = (long)TOK*HID, EG = (long)NE*HID;
    const long EU = (long)NE*GUD*HID, ED = (long)NE*HID*IMD;

    const float *x = nullptr, *gw = nullptr, *wgu = nullptr, *wd = nullptr;
    for (int i = 0; i < n_in; i++) {
        long sz = in_sizes[i];
        if      (sz == EX && !x)   x   = (const float*)d_in[i];
        else if (sz == EG && !gw)  gw  = (const float*)d_in[i];
        else if (sz == EU && !wgu) wgu = (const float*)d_in[i];
        else if (sz == ED && !wd)  wd  = (const float*)d_in[i];
    }
    if (!x || !gw || !wgu || !wd) {
        if (n_in < 4) return;
        x = (const float*)d_in[0]; gw = (const float*)d_in[1];
        wgu = (const float*)d_in[2]; wd = (const float*)d_in[3];
    }
    cudaFuncSetAttribute(k_moe, cudaFuncAttributeMaxDynamicSharedMemorySize, SMEM_BYTES);
    k_moe<<<NBLK, NTH, SMEM_BYTES>>>(x, gw, wgu, wd, (float*)d_out);
}

// round 11
// speedup vs baseline: 1.6583x; 1.6583x over previous
#include <cuda_runtime.h>
#include <cuda_bf16.h>
#include <math.h>
#include <stdint.h>

#define TOK 1024
#define HID 2048
#define IMD 768
#define GUD 1536
#define NE  8
#define NBLK 148
#define NTH 512
#define NT (NBLK*NTH)

// ---- per-stage smem: 4 matrices of 128 rows x 64 bf16 (swizzled 128B rows) ----
#define SA_H 0
#define SA_L 16384
#define SB_H 32768
#define SB_L 49152
#define STAGE_BYTES 65536
#define NSTG 3
#define SMEM_BYTES (NSTG*STAGE_BYTES)

// ---------------- scratch (device globals) ----------------
__device__ __align__(16) int   g_cnt[NE];     // zeroed at END of every launch
__device__ __align__(16) int   g_list[NE*TOK];
__device__ __align__(16) float g_topw[2*TOK];
__device__ __align__(16) float g_gu[2*TOK*GUD];
__device__ __align__(16) float g_o2[2*TOK*HID];
__device__ __align__(16) __nv_bfloat16 g_xh [TOK*HID],     g_xl [TOK*HID];
__device__ __align__(16) __nv_bfloat16 g_wuh[NE*GUD*HID],  g_wul[NE*GUD*HID];
__device__ __align__(16) __nv_bfloat16 g_wdh[NE*HID*IMD],  g_wdl[NE*HID*IMD];
__device__ __align__(16) __nv_bfloat16 g_hbh[2*TOK*IMD],   g_hbl[2*TOK*IMD];
__device__ unsigned          g_bcnt   = 0;
__device__ volatile unsigned g_bsense = 0;

// ---------------- helpers ----------------
__device__ __forceinline__ uint32_t smem_u32(const void* p) {
    uint32_t a;
    asm("{ .reg .u64 t; cvta.to.shared.u64 t, %1; cvt.u32.u64 %0, t; }" : "=r"(a) : "l"(p));
    return a;
}
__device__ __forceinline__ void cp16(uint32_t dst, const void* src) {
    asm volatile("cp.async.cg.shared.global [%0], [%1], 16;" :: "r"(dst), "l"(src) : "memory");
}
__device__ __forceinline__ void cp16p(uint32_t dst, const void* src, int full) {
    asm volatile("cp.async.cg.shared.global [%0], [%1], 16, %2;"
                 :: "r"(dst), "l"(src), "r"(full ? 16 : 0) : "memory");
}
#define CP_COMMIT() asm volatile("cp.async.commit_group;" ::: "memory")
#define CP_WAIT(n)  asm volatile("cp.async.wait_group %0;" :: "n"(n) : "memory")

__device__ __forceinline__ void ldsm_x4(uint32_t r[4], uint32_t addr) {
    asm volatile("ldmatrix.sync.aligned.m8n8.x4.shared.b16 {%0,%1,%2,%3}, [%4];"
        : "=r"(r[0]), "=r"(r[1]), "=r"(r[2]), "=r"(r[3]) : "r"(addr));
}
__device__ __forceinline__ void mma_bf16(float c[4], const uint32_t a[4], const uint32_t b[2]) {
    asm volatile("mma.sync.aligned.m16n8k16.row.col.f32.bf16.bf16.f32 "
        "{%0,%1,%2,%3}, {%4,%5,%6,%7}, {%8,%9}, {%0,%1,%2,%3};"
        : "+f"(c[0]), "+f"(c[1]), "+f"(c[2]), "+f"(c[3])
        : "r"(a[0]), "r"(a[1]), "r"(a[2]), "r"(a[3]), "r"(b[0]), "r"(b[1]));
}
__device__ __forceinline__ void split4(float4 v, uint2& hi, uint2& lo) {
    __nv_bfloat16 h0 = __float2bfloat16(v.x), h1 = __float2bfloat16(v.y);
    __nv_bfloat16 h2 = __float2bfloat16(v.z), h3 = __float2bfloat16(v.w);
    __nv_bfloat16 l0 = __float2bfloat16(v.x - __bfloat162float(h0));
    __nv_bfloat16 l1 = __float2bfloat16(v.y - __bfloat162float(h1));
    __nv_bfloat16 l2 = __float2bfloat16(v.z - __bfloat162float(h2));
    __nv_bfloat16 l3 = __float2bfloat16(v.w - __bfloat162float(h3));
    hi.x = (uint32_t)__bfloat16_as_ushort(h0) | ((uint32_t)__bfloat16_as_ushort(h1) << 16);
    hi.y = (uint32_t)__bfloat16_as_ushort(h2) | ((uint32_t)__bfloat16_as_ushort(h3) << 16);
    lo.x = (uint32_t)__bfloat16_as_ushort(l0) | ((uint32_t)__bfloat16_as_ushort(l1) << 16);
    lo.y = (uint32_t)__bfloat16_as_ushort(l2) | ((uint32_t)__bfloat16_as_ushort(l3) << 16);
}
__device__ __forceinline__ void gbar(unsigned& ls) {
    __syncthreads();
    if (threadIdx.x == 0) {
        unsigned target = ls + 1u;
        __threadfence();
        unsigned old = atomicAdd(&g_bcnt, 1u);
        if (old == NBLK - 1u) { g_bcnt = 0u; __threadfence(); g_bsense = target; }
        else { while (g_bsense != target) __nanosleep(128); }
        __threadfence();
    }
    ls += 1u;
    __syncthreads();
}
__device__ __forceinline__ float wsum(float v) {
#pragma unroll
    for (int o = 16; o; o >>= 1) v += __shfl_xor_sync(0xffffffffu, v, o);
    return v;
}

// ------- 128x128xK warp-MMA tile (16 warps of 32x32), 3-stage cp.async -------
// Inner loop is TERM-MAJOR: per ks, all fragments are loaded first, then the
// 3 split terms (hh, hl, lh) are each issued across all 8 accumulators, so
// same-accumulator MMAs are 8 instructions apart (no RAW stall).
template<int KD, bool SECOND>
__device__ __forceinline__ void mma_tile(
    const __nv_bfloat16* __restrict__ Ah, const __nv_bfloat16* __restrict__ Al,
    const __nv_bfloat16* __restrict__ Bh, const __nv_bfloat16* __restrict__ Bl,
    int e, int m0, int n0, int ne, char* sm, uint32_t sb)
{
    const int tid = threadIdx.x;
    const int wid = tid >> 5, lane = tid & 31;

    // ---- global->smem mapping: thread = (row=tid>>2, 2 chunks of 16B per matrix) ----
    const int lrow = tid >> 2;
    const int cq   = (tid & 3) * 2;
    const int a_ok = (m0 + lrow < ne);
    const uint4 *agh, *agl;
    {
        int pair = a_ok ? g_list[e*TOK + m0 + lrow] : 0;
        size_t ar = (size_t)(SECOND ? pair : (pair >> 1)) * KD;
        agh = (const uint4*)(Ah + ar);
        agl = (const uint4*)(Al + ar);
    }
    const uint4* bgh = (const uint4*)(Bh + (size_t)(n0 + lrow) * KD);
    const uint4* bgl = (const uint4*)(Bl + (size_t)(n0 + lrow) * KD);

    uint32_t sts[2];
#pragma unroll
    for (int j = 0; j < 2; j++) {
        int ch = cq + j;
        sts[j] = (uint32_t)(lrow * 128 + ((ch ^ (lrow & 7)) << 4));
    }

    const int KBN = KD / 64;
    auto issue = [&](int kb, int stg) {
        uint32_t base = sb + (uint32_t)stg * STAGE_BYTES;
#pragma unroll
        for (int j = 0; j < 2; j++) {
            int ch = cq + j;
            cp16p(base + SA_H + sts[j], agh + kb*8 + ch, a_ok);
            cp16p(base + SA_L + sts[j], agl + kb*8 + ch, a_ok);
            cp16 (base + SB_H + sts[j], bgh + kb*8 + ch);
            cp16 (base + SB_L + sts[j], bgl + kb*8 + ch);
        }
        CP_COMMIT();
    };

    // ---- warp tile: 32m x 32n, warp grid 4x4 ----
    const int wm = (wid & 3) * 32;
    const int wn = (wid >> 2) * 32;
    const int q  = lane >> 3, r8 = lane & 7;
    const int a_m_base = wm + (q & 1) * 8 + r8;
    const int a_ch_off = (q >> 1);
    const int b_n_base = wn + (q >> 1) * 8 + r8;
    const int b_ch_off = (q & 1);

    float acc[2][4][4];
#pragma unroll
    for (int i = 0; i < 2; i++)
#pragma unroll
        for (int j = 0; j < 4; j++)
#pragma unroll
            for (int c = 0; c < 4; c++) acc[i][j][c] = 0.f;

    issue(0, 0);
    if (KBN > 1) issue(1, 1);

    for (int kb = 0; kb < KBN; kb++) {
        const int stg = kb % NSTG;
        if (kb == KBN - 1) { CP_WAIT(0); } else { CP_WAIT(1); }
        __syncthreads();
        if (kb + 2 < KBN) issue(kb + 2, (kb + 2) % NSTG);

        const uint32_t base = sb + (uint32_t)stg * STAGE_BYTES;
        const uint32_t saH = base + SA_H, saL = base + SA_L;
        const uint32_t sbH = base + SB_H, sbL = base + SB_L;

#pragma unroll
        for (int ks = 0; ks < 4; ks++) {
            // -------- load ALL fragments for this ks --------
            uint32_t ahf[2][4], alf[2][4], bhf[2][4], blf[2][4];
#pragma unroll
            for (int mi = 0; mi < 2; mi++) {
                int m_ld = a_m_base + mi * 16;
                uint32_t off = (uint32_t)(m_ld * 128 + (((ks*2 + a_ch_off) ^ (m_ld & 7)) << 4));
                ldsm_x4(ahf[mi], saH + off);
                ldsm_x4(alf[mi], saL + off);
            }
#pragma unroll
            for (int nb = 0; nb < 2; nb++) {
                int n_ld = b_n_base + nb * 16;
                uint32_t off = (uint32_t)(n_ld * 128 + (((ks*2 + b_ch_off) ^ (n_ld & 7)) << 4));
                ldsm_x4(bhf[nb], sbH + off);
                ldsm_x4(blf[nb], sbL + off);
            }
            // -------- term-major MMA issue: hh, hl, lh (8 independent each) --------
#pragma unroll
            for (int mi = 0; mi < 2; mi++)
#pragma unroll
                for (int nb = 0; nb < 2; nb++)
#pragma unroll
                    for (int h = 0; h < 2; h++)
                        mma_bf16(acc[mi][nb*2 + h], ahf[mi], &bhf[nb][2*h]);
#pragma unroll
            for (int mi = 0; mi < 2; mi++)
#pragma unroll
                for (int nb = 0; nb < 2; nb++)
#pragma unroll
                    for (int h = 0; h < 2; h++)
                        mma_bf16(acc[mi][nb*2 + h], ahf[mi], &blf[nb][2*h]);
#pragma unroll
            for (int mi = 0; mi < 2; mi++)
#pragma unroll
                for (int nb = 0; nb < 2; nb++)
#pragma unroll
                    for (int h = 0; h < 2; h++)
                        mma_bf16(acc[mi][nb*2 + h], alf[mi], &bhf[nb][2*h]);
        }
    }

    // ---- epilogue ----
    const int g  = lane >> 2, t4 = lane & 3;
#pragma unroll
    for (int mi = 0; mi < 2; mi++) {
        int mr0 = m0 + wm + mi*16 + g;
        int mr1 = mr0 + 8;
        float* row0 = nullptr; float* row1 = nullptr;
        if (mr0 < ne) {
            int p = g_list[e*TOK + mr0];
            row0 = SECOND ? (g_o2 + (size_t)p * HID) : (g_gu + (size_t)p * GUD);
        }
        if (mr1 < ne) {
            int p = g_list[e*TOK + mr1];
            row1 = SECOND ? (g_o2 + (size_t)p * HID) : (g_gu + (size_t)p * GUD);
        }
#pragma unroll
        for (int nj = 0; nj < 4; nj++) {
            int n = n0 + wn + nj*8 + t4*2;
            if (row0) *(float2*)(row0 + n) = make_float2(acc[mi][nj][0], acc[mi][nj][1]);
            if (row1) *(float2*)(row1 + n) = make_float2(acc[mi][nj][2], acc[mi][nj][3]);
        }
    }
    __syncthreads();
}

// ---------------- persistent fused MoE kernel ----------------
__global__ void __launch_bounds__(NTH) k_moe(
    const float* __restrict__ x,   const float* __restrict__ gw,
    const float* __restrict__ wgu, const float* __restrict__ wd,
    float* __restrict__ out)
{
    extern __shared__ char sm[];
    const uint32_t sb = smem_u32(sm);
    const int tid  = threadIdx.x;
    const int wid  = tid >> 5;
    const int lane = tid & 31;
    const int bid  = blockIdx.x;
    const int gtid = bid * NTH + tid;
    unsigned ls = g_bsense;

    // ---- P0: router + split inputs/weights (g_cnt arrives zeroed from prior launch) ----
    {
        // router: one warp per token (CTAs 0..63)
        int t = bid * 16 + wid;
        if (t < TOK) {
            const float* xr = x + (size_t)t * HID;
            float acc[NE];
#pragma unroll
            for (int e2 = 0; e2 < NE; e2++) acc[e2] = 0.f;
            for (int j = lane; j < HID; j += 32) {
                float xv = xr[j];
#pragma unroll
                for (int e2 = 0; e2 < NE; e2++) acc[e2] += xv * gw[e2*HID + j];
            }
#pragma unroll
            for (int e2 = 0; e2 < NE; e2++) acc[e2] = wsum(acc[e2]);
            if (lane == 0) {
                int i1 = 0; float v1 = acc[0];
#pragma unroll
                for (int e2 = 1; e2 < NE; e2++) if (acc[e2] > v1) { v1 = acc[e2]; i1 = e2; }
                int i2 = (i1 == 0) ? 1 : 0; float v2 = acc[i2];
#pragma unroll
                for (int e2 = 0; e2 < NE; e2++) if (e2 != i1 && acc[e2] > v2) { v2 = acc[e2]; i2 = e2; }
                float r  = expf(v2 - v1);          // full-E softmax + top-2 renorm
                float w1 = 1.f / (1.f + r);        // == 2-way softmax over {v1,v2}
                g_topw[2*t+0] = w1;
                g_topw[2*t+1] = r * w1;
                int p1 = atomicAdd(&g_cnt[i1], 1); g_list[i1*TOK + p1] = 2*t + 0;
                int p2 = atomicAdd(&g_cnt[i2], 1); g_list[i2*TOK + p2] = 2*t + 1;
            }
        }
        // split x, Wgu, Wd into bf16 hi/lo
        uint2 hi, lo;
        for (long i = gtid; i < (long)TOK*HID/4; i += NT) {
            split4(((const float4*)x)[i], hi, lo);
            ((uint2*)g_xh)[i] = hi; ((uint2*)g_xl)[i] = lo;
        }
        for (long i = gtid; i < (long)NE*GUD*HID/4; i += NT) {
            split4(((const float4*)wgu)[i], hi, lo);
            ((uint2*)g_wuh)[i] = hi; ((uint2*)g_wul)[i] = lo;
        }
        for (long i = gtid; i < (long)NE*HID*IMD/4; i += NT) {
            split4(((const float4*)wd)[i], hi, lo);
            ((uint2*)g_wdh)[i] = hi; ((uint2*)g_wdl)[i] = lo;
        }
    }
    gbar(ls);

    // ---- P2: GEMM1  x @ Wgu^T -> g_gu  (K=2048, N=1536) ----
    for (int job = bid; job < NE*8*12; job += NBLK) {
        int e  = job / 96;
        int mt = (job % 96) / 12;
        int nt = job % 12;
        int ne = g_cnt[e];
        if (mt * 128 >= ne) continue;
        mma_tile<HID, false>(g_xh, g_xl,
                             g_wuh + (size_t)e*GUD*HID, g_wul + (size_t)e*GUD*HID,
                             e, mt*128, nt*128, ne, sm, sb);
    }
    gbar(ls);

    // ---- P3: act h = silu(g)*u -> bf16 hi/lo ----
    {
        const int n4 = 2*TOK*IMD/4;
        for (int i = gtid; i < n4; i += NT) {
            int p  = i / (IMD/4);
            int j4 = i - p * (IMD/4);
            float4 g4 = *(const float4*)(g_gu + (size_t)p*GUD + 4*j4);
            float4 u4 = *(const float4*)(g_gu + (size_t)p*GUD + IMD + 4*j4);
            float4 h4;
            h4.x = (g4.x / (1.f + expf(-g4.x))) * u4.x;
            h4.y = (g4.y / (1.f + expf(-g4.y))) * u4.y;
            h4.z = (g4.z / (1.f + expf(-g4.z))) * u4.z;
            h4.w = (g4.w / (1.f + expf(-g4.w))) * u4.w;
            uint2 hi, lo;
            split4(h4, hi, lo);
            ((uint2*)g_hbh)[i] = hi; ((uint2*)g_hbl)[i] = lo;
        }
    }
    gbar(ls);

    // ---- P4: GEMM2  h @ Wd^T -> g_o2  (K=768, N=2048) ----
    for (int job = bid; job < NE*8*16; job += NBLK) {
        int e  = job / 128;
        int mt = (job % 128) / 16;
        int nt = job % 16;
        int ne = g_cnt[e];
        if (mt * 128 >= ne) continue;
        mma_tile<IMD, true>(g_hbh, g_hbl,
                            g_wdh + (size_t)e*HID*IMD, g_wdl + (size_t)e*HID*IMD,
                            e, mt*128, nt*128, ne, sm, sb);
    }
    gbar(ls);

    // ---- P5: combine out[t] = w1*y[2t] + w2*y[2t+1]; reset g_cnt for next launch ----
    {
        const int n4 = TOK*HID/4;
        for (int i = gtid; i < n4; i += NT) {
            int t  = i / (HID/4);
            int j4 = i - t * (HID/4);
            float w1 = g_topw[2*t+0], w2 = g_topw[2*t+1];
            float4 y1 = ((const float4*)g_o2)[(size_t)(2*t  )*(HID/4) + j4];
            float4 y2 = ((const float4*)g_o2)[(size_t)(2*t+1)*(HID/4) + j4];
            float4 o;
            o.x = w1*y1.x + w2*y2.x;
            o.y = w1*y1.y + w2*y2.y;
            o.z = w1*y1.z + w2*y2.z;
            o.w = w1*y1.w + w2*y2.w;
            ((float4*)out)[i] = o;
        }
        if (bid == 0 && tid < NE) g_cnt[tid] = 0;   // P4 done grid-wide (gbar above)
    }
}

// ---------------- launch ----------------
extern "C" void kernel_launch(void* const* d_in, const int* in_sizes, int n_in,
                              void* d_out, int out_size) {
    const long EX = (long)TOK*HID, EG = (long)NE*HID;
    const long EU = (long)NE*GUD*HID, ED = (long)NE*HID*IMD;

    const float *x = nullptr, *gw = nullptr, *wgu = nullptr, *wd = nullptr;
    for (int i = 0; i < n_in; i++) {
        long sz = in_sizes[i];
        if      (sz == EX && !x)   x   = (const float*)d_in[i];
        else if (sz == EG && !gw)  gw  = (const float*)d_in[i];
        else if (sz == EU && !wgu) wgu = (const float*)d_in[i];
        else if (sz == ED && !wd)  wd  = (const float*)d_in[i];
    }
    if (!x || !gw || !wgu || !wd) {
        if (n_in < 4) return;
        x = (const float*)d_in[0]; gw = (const float*)d_in[1];
        wgu = (const float*)d_in[2]; wd = (const float*)d_in[3];
    }
    cudaFuncSetAttribute(k_moe, cudaFuncAttributeMaxDynamicSharedMemorySize, SMEM_BYTES);
    k_moe<<<NBLK, NTH, SMEM_BYTES>>>(x, gw, wgu, wd, (float*)d_out);
}

// round 12
// speedup vs baseline: 2.0346x; 1.2269x over previous
#include <cuda_runtime.h>
#include <cuda_bf16.h>
#include <math.h>
#include <stdint.h>

#define TOK 1024
#define HID 2048
#define IMD 768
#define GUD 1536
#define NE  8
#define NBLK 148
#define NTH 512
#define NT (NBLK*NTH)

// ---- per-stage smem: 4 matrices of 128 rows x 64 bf16 (swizzled 128B rows) ----
#define SA_H 0
#define SA_L 16384
#define SB_H 32768
#define SB_L 49152
#define STAGE_BYTES 65536
#define NSTG 3
#define SMEM_BYTES (NSTG*STAGE_BYTES)

// ---------------- scratch (device globals) ----------------
__device__ __align__(16) int   g_cnt[NE];     // zeroed at END of every launch
__device__ __align__(16) int   g_list[NE*TOK];
__device__ __align__(16) float g_topw[2*TOK];
__device__ __align__(16) float g_gu[2*TOK*GUD];
__device__ __align__(16) float g_o2[2*TOK*HID];
__device__ __align__(16) __nv_bfloat16 g_xh [TOK*HID],     g_xl [TOK*HID];
__device__ __align__(16) __nv_bfloat16 g_wuh[NE*GUD*HID],  g_wul[NE*GUD*HID];
__device__ __align__(16) __nv_bfloat16 g_wdh[NE*HID*IMD],  g_wdl[NE*HID*IMD];
__device__ __align__(16) __nv_bfloat16 g_hbh[2*TOK*IMD],   g_hbl[2*TOK*IMD];
__device__ unsigned          g_bcnt   = 0;
__device__ volatile unsigned g_bsense = 0;

// ---------------- helpers ----------------
__device__ __forceinline__ uint32_t smem_u32(const void* p) {
    uint32_t a;
    asm("{ .reg .u64 t; cvta.to.shared.u64 t, %1; cvt.u32.u64 %0, t; }" : "=r"(a) : "l"(p));
    return a;
}
__device__ __forceinline__ void cp16(uint32_t dst, const void* src) {
    asm volatile("cp.async.cg.shared.global [%0], [%1], 16;" :: "r"(dst), "l"(src) : "memory");
}
__device__ __forceinline__ void cp16p(uint32_t dst, const void* src, int full) {
    asm volatile("cp.async.cg.shared.global [%0], [%1], 16, %2;"
                 :: "r"(dst), "l"(src), "r"(full ? 16 : 0) : "memory");
}
#define CP_COMMIT() asm volatile("cp.async.commit_group;" ::: "memory")
#define CP_WAIT(n)  asm volatile("cp.async.wait_group %0;" :: "n"(n) : "memory")

__device__ __forceinline__ void ldsm_x4(uint32_t r[4], uint32_t addr) {
    asm volatile("ldmatrix.sync.aligned.m8n8.x4.shared.b16 {%0,%1,%2,%3}, [%4];"
        : "=r"(r[0]), "=r"(r[1]), "=r"(r[2]), "=r"(r[3]) : "r"(addr));
}
__device__ __forceinline__ void mma_bf16(float c[4], const uint32_t a[4], const uint32_t b[2]) {
    asm volatile("mma.sync.aligned.m16n8k16.row.col.f32.bf16.bf16.f32 "
        "{%0,%1,%2,%3}, {%4,%5,%6,%7}, {%8,%9}, {%0,%1,%2,%3};"
        : "+f"(c[0]), "+f"(c[1]), "+f"(c[2]), "+f"(c[3])
        : "r"(a[0]), "r"(a[1]), "r"(a[2]), "r"(a[3]), "r"(b[0]), "r"(b[1]));
}
__device__ __forceinline__ void split4(float4 v, uint2& hi, uint2& lo) {
    __nv_bfloat16 h0 = __float2bfloat16(v.x), h1 = __float2bfloat16(v.y);
    __nv_bfloat16 h2 = __float2bfloat16(v.z), h3 = __float2bfloat16(v.w);
    __nv_bfloat16 l0 = __float2bfloat16(v.x - __bfloat162float(h0));
    __nv_bfloat16 l1 = __float2bfloat16(v.y - __bfloat162float(h1));
    __nv_bfloat16 l2 = __float2bfloat16(v.z - __bfloat162float(h2));
    __nv_bfloat16 l3 = __float2bfloat16(v.w - __bfloat162float(h3));
    hi.x = (uint32_t)__bfloat16_as_ushort(h0) | ((uint32_t)__bfloat16_as_ushort(h1) << 16);
    hi.y = (uint32_t)__bfloat16_as_ushort(h2) | ((uint32_t)__bfloat16_as_ushort(h3) << 16);
    lo.x = (uint32_t)__bfloat16_as_ushort(l0) | ((uint32_t)__bfloat16_as_ushort(l1) << 16);
    lo.y = (uint32_t)__bfloat16_as_ushort(l2) | ((uint32_t)__bfloat16_as_ushort(l3) << 16);
}
__device__ __forceinline__ void gbar(unsigned& ls) {
    __syncthreads();
    if (threadIdx.x == 0) {
        unsigned target = ls + 1u;
        __threadfence();
        unsigned old = atomicAdd(&g_bcnt, 1u);
        if (old == NBLK - 1u) { g_bcnt = 0u; __threadfence(); g_bsense = target; }
        else { while (g_bsense != target) __nanosleep(128); }
        __threadfence();
    }
    ls += 1u;
    __syncthreads();
}
__device__ __forceinline__ float wsum(float v) {
#pragma unroll
    for (int o = 16; o; o >>= 1) v += __shfl_xor_sync(0xffffffffu, v, o);
    return v;
}

// ------- 128x128xK warp-MMA tile (16 warps of 32x32), 3-stage cp.async -------
template<int KD, bool SECOND>
__device__ __forceinline__ void mma_tile(
    const __nv_bfloat16* __restrict__ Ah, const __nv_bfloat16* __restrict__ Al,
    const __nv_bfloat16* __restrict__ Bh, const __nv_bfloat16* __restrict__ Bl,
    int e, int m0, int n0, int ne, char* sm, uint32_t sb)
{
    const int tid = threadIdx.x;
    const int wid = tid >> 5, lane = tid & 31;

    // ---- global->smem mapping: thread = (row=tid>>2, 2 chunks of 16B per matrix) ----
    const int lrow = tid >> 2;
    const int cq   = (tid & 3) * 2;
    const int a_ok = (m0 + lrow < ne);
    const uint4 *agh, *agl;
    {
        int pair = a_ok ? g_list[e*TOK + m0 + lrow] : 0;
        size_t ar = (size_t)(SECOND ? pair : (pair >> 1)) * KD;
        agh = (const uint4*)(Ah + ar);
        agl = (const uint4*)(Al + ar);
    }
    const uint4* bgh = (const uint4*)(Bh + (size_t)(n0 + lrow) * KD);
    const uint4* bgl = (const uint4*)(Bl + (size_t)(n0 + lrow) * KD);

    uint32_t sts[2];
#pragma unroll
    for (int j = 0; j < 2; j++) {
        int ch = cq + j;
        sts[j] = (uint32_t)(lrow * 128 + ((ch ^ (lrow & 7)) << 4));
    }

    const int KBN = KD / 64;
    auto issue = [&](int kb, int stg) {
        uint32_t base = sb + (uint32_t)stg * STAGE_BYTES;
#pragma unroll
        for (int j = 0; j < 2; j++) {
            int ch = cq + j;
            cp16p(base + SA_H + sts[j], agh + kb*8 + ch, a_ok);
            cp16p(base + SA_L + sts[j], agl + kb*8 + ch, a_ok);
            cp16 (base + SB_H + sts[j], bgh + kb*8 + ch);
            cp16 (base + SB_L + sts[j], bgl + kb*8 + ch);
        }
        CP_COMMIT();
    };

    // ---- warp tile: 32m x 32n, warp grid 4x4 ----
    const int wm = (wid & 3) * 32;
    const int wn = (wid >> 2) * 32;
    const int q  = lane >> 3, r8 = lane & 7;
    const int a_m_base = wm + (q & 1) * 8 + r8;
    const int a_ch_off = (q >> 1);
    const int b_n_base = wn + (q >> 1) * 8 + r8;
    const int b_ch_off = (q & 1);

    float acc[2][4][4];
#pragma unroll
    for (int i = 0; i < 2; i++)
#pragma unroll
        for (int j = 0; j < 4; j++)
#pragma unroll
            for (int c = 0; c < 4; c++) acc[i][j][c] = 0.f;

    issue(0, 0);
    if (KBN > 1) issue(1, 1);

    for (int kb = 0; kb < KBN; kb++) {
        const int stg = kb % NSTG;
        if (kb == KBN - 1) { CP_WAIT(0); } else { CP_WAIT(1); }
        __syncthreads();
        if (kb + 2 < KBN) issue(kb + 2, (kb + 2) % NSTG);

        const uint32_t base = sb + (uint32_t)stg * STAGE_BYTES;
        const uint32_t saH = base + SA_H, saL = base + SA_L;
        const uint32_t sbH = base + SB_H, sbL = base + SB_L;

#pragma unroll
        for (int ks = 0; ks < 4; ks++) {
            uint32_t ahf[2][4], alf[2][4], bhf[2][4], blf[2][4];
#pragma unroll
            for (int mi = 0; mi < 2; mi++) {
                int m_ld = a_m_base + mi * 16;
                uint32_t off = (uint32_t)(m_ld * 128 + (((ks*2 + a_ch_off) ^ (m_ld & 7)) << 4));
                ldsm_x4(ahf[mi], saH + off);
                ldsm_x4(alf[mi], saL + off);
            }
#pragma unroll
            for (int nb = 0; nb < 2; nb++) {
                int n_ld = b_n_base + nb * 16;
                uint32_t off = (uint32_t)(n_ld * 128 + (((ks*2 + b_ch_off) ^ (n_ld & 7)) << 4));
                ldsm_x4(bhf[nb], sbH + off);
                ldsm_x4(blf[nb], sbL + off);
            }
#pragma unroll
            for (int mi = 0; mi < 2; mi++)
#pragma unroll
                for (int nb = 0; nb < 2; nb++)
#pragma unroll
                    for (int h = 0; h < 2; h++)
                        mma_bf16(acc[mi][nb*2 + h], ahf[mi], &bhf[nb][2*h]);
#pragma unroll
            for (int mi = 0; mi < 2; mi++)
#pragma unroll
                for (int nb = 0; nb < 2; nb++)
#pragma unroll
                    for (int h = 0; h < 2; h++)
                        mma_bf16(acc[mi][nb*2 + h], ahf[mi], &blf[nb][2*h]);
#pragma unroll
            for (int mi = 0; mi < 2; mi++)
#pragma unroll
                for (int nb = 0; nb < 2; nb++)
#pragma unroll
                    for (int h = 0; h < 2; h++)
                        mma_bf16(acc[mi][nb*2 + h], alf[mi], &bhf[nb][2*h]);
        }
    }

    // ---- epilogue ----
    const int g  = lane >> 2, t4 = lane & 3;
#pragma unroll
    for (int mi = 0; mi < 2; mi++) {
        int mr0 = m0 + wm + mi*16 + g;
        int mr1 = mr0 + 8;
        float* row0 = nullptr; float* row1 = nullptr;
        if (mr0 < ne) {
            int p = g_list[e*TOK + mr0];
            row0 = SECOND ? (g_o2 + (size_t)p * HID) : (g_gu + (size_t)p * GUD);
        }
        if (mr1 < ne) {
            int p = g_list[e*TOK + mr1];
            row1 = SECOND ? (g_o2 + (size_t)p * HID) : (g_gu + (size_t)p * GUD);
        }
#pragma unroll
        for (int nj = 0; nj < 4; nj++) {
            int n = n0 + wn + nj*8 + t4*2;
            if (row0) *(float2*)(row0 + n) = make_float2(acc[mi][nj][0], acc[mi][nj][1]);
            if (row1) *(float2*)(row1 + n) = make_float2(acc[mi][nj][2], acc[mi][nj][3]);
        }
    }
    __syncthreads();
}

// ---------------- persistent fused MoE kernel ----------------
__global__ void __launch_bounds__(NTH) k_moe(
    const float* __restrict__ x,   const float* __restrict__ gw,
    const float* __restrict__ wgu, const float* __restrict__ wd,
    float* __restrict__ out)
{
    extern __shared__ char sm[];
    const uint32_t sb = smem_u32(sm);
    const int tid  = threadIdx.x;
    const int wid  = tid >> 5;
    const int lane = tid & 31;
    const int bid  = blockIdx.x;
    const int gtid = bid * NTH + tid;
    unsigned ls = g_bsense;

    // ---- P0: router + split inputs/weights (g_cnt arrives zeroed) ----
    {
        int t = bid * 16 + wid;
        if (t < TOK) {
            const float* xr = x + (size_t)t * HID;
            float acc[NE];
#pragma unroll
            for (int e2 = 0; e2 < NE; e2++) acc[e2] = 0.f;
            for (int j = lane; j < HID; j += 32) {
                float xv = xr[j];
#pragma unroll
                for (int e2 = 0; e2 < NE; e2++) acc[e2] += xv * gw[e2*HID + j];
            }
#pragma unroll
            for (int e2 = 0; e2 < NE; e2++) acc[e2] = wsum(acc[e2]);
            if (lane == 0) {
                int i1 = 0; float v1 = acc[0];
#pragma unroll
                for (int e2 = 1; e2 < NE; e2++) if (acc[e2] > v1) { v1 = acc[e2]; i1 = e2; }
                int i2 = (i1 == 0) ? 1 : 0; float v2 = acc[i2];
#pragma unroll
                for (int e2 = 0; e2 < NE; e2++) if (e2 != i1 && acc[e2] > v2) { v2 = acc[e2]; i2 = e2; }
                float r  = expf(v2 - v1);          // full-E softmax + top-2 renorm
                float w1 = 1.f / (1.f + r);        // == 2-way softmax over {v1,v2}
                g_topw[2*t+0] = w1;
                g_topw[2*t+1] = r * w1;
                int p1 = atomicAdd(&g_cnt[i1], 1); g_list[i1*TOK + p1] = 2*t + 0;
                int p2 = atomicAdd(&g_cnt[i2], 1); g_list[i2*TOK + p2] = 2*t + 1;
            }
        }
        uint2 hi, lo;
        for (long i = gtid; i < (long)TOK*HID/4; i += NT) {
            split4(((const float4*)x)[i], hi, lo);
            ((uint2*)g_xh)[i] = hi; ((uint2*)g_xl)[i] = lo;
        }
        for (long i = gtid; i < (long)NE*GUD*HID/4; i += NT) {
            split4(((const float4*)wgu)[i], hi, lo);
            ((uint2*)g_wuh)[i] = hi; ((uint2*)g_wul)[i] = lo;
        }
        for (long i = gtid; i < (long)NE*HID*IMD/4; i += NT) {
            split4(((const float4*)wd)[i], hi, lo);
            ((uint2*)g_wdh)[i] = hi; ((uint2*)g_wdl)[i] = lo;
        }
    }
    gbar(ls);

    // ---- build compact m-tile table (redundantly per CTA; 8 loads) ----
    int cnt[NE], cmt[NE+1];
    cmt[0] = 0;
#pragma unroll
    for (int e2 = 0; e2 < NE; e2++) {
        cnt[e2] = g_cnt[e2];
        cmt[e2+1] = cmt[e2] + ((cnt[e2] + 127) >> 7);
    }
    const int total_mt = cmt[NE];

    // ---- P2: GEMM1  x @ Wgu^T -> g_gu  (dense job list: total_mt x 12) ----
    for (int job = bid; job < total_mt * 12; job += NBLK) {
        int jm = job / 12, nt = job % 12;
        int e = 0;
#pragma unroll
        for (int e2 = 0; e2 < NE; e2++) if (jm >= cmt[e2+1]) e = e2 + 1;
        int mt = jm - cmt[e];
        mma_tile<HID, false>(g_xh, g_xl,
                             g_wuh + (size_t)e*GUD*HID, g_wul + (size_t)e*GUD*HID,
                             e, mt*128, nt*128, cnt[e], sm, sb);
    }
    gbar(ls);

    // ---- P3: act h = silu(g)*u -> bf16 hi/lo ----
    {
        const int n4 = 2*TOK*IMD/4;
        for (int i = gtid; i < n4; i += NT) {
            int p  = i / (IMD/4);
            int j4 = i - p * (IMD/4);
            float4 g4 = *(const float4*)(g_gu + (size_t)p*GUD + 4*j4);
            float4 u4 = *(const float4*)(g_gu + (size_t)p*GUD + IMD + 4*j4);
            float4 h4;
            h4.x = (g4.x / (1.f + expf(-g4.x))) * u4.x;
            h4.y = (g4.y / (1.f + expf(-g4.y))) * u4.y;
            h4.z = (g4.z / (1.f + expf(-g4.z))) * u4.z;
            h4.w = (g4.w / (1.f + expf(-g4.w))) * u4.w;
            uint2 hi, lo;
            split4(h4, hi, lo);
            ((uint2*)g_hbh)[i] = hi; ((uint2*)g_hbl)[i] = lo;
        }
    }
    gbar(ls);

    // ---- P4: GEMM2  h @ Wd^T -> g_o2  (dense job list: total_mt x 16) ----
    for (int job = bid; job < total_mt * 16; job += NBLK) {
        int jm = job / 16, nt = job % 16;
        int e = 0;
#pragma unroll
        for (int e2 = 0; e2 < NE; e2++) if (jm >= cmt[e2+1]) e = e2 + 1;
        int mt = jm - cmt[e];
        mma_tile<IMD, true>(g_hbh, g_hbl,
                            g_wdh + (size_t)e*HID*IMD, g_wdl + (size_t)e*HID*IMD,
                            e, mt*128, nt*128, cnt[e], sm, sb);
    }
    gbar(ls);

    // ---- P5: combine out[t] = w1*y[2t] + w2*y[2t+1]; reset g_cnt ----
    {
        const int n4 = TOK*HID/4;
        for (int i = gtid; i < n4; i += NT) {
            int t  = i / (HID/4);
            int j4 = i - t * (HID/4);
            float w1 = g_topw[2*t+0], w2 = g_topw[2*t+1];
            float4 y1 = ((const float4*)g_o2)[(size_t)(2*t  )*(HID/4) + j4];
            float4 y2 = ((const float4*)g_o2)[(size_t)(2*t+1)*(HID/4) + j4];
            float4 o;
            o.x = w1*y1.x + w2*y2.x;
            o.y = w1*y1.y + w2*y2.y;
            o.z = w1*y1.z + w2*y2.z;
            o.w = w1*y1.w + w2*y2.w;
            ((float4*)out)[i] = o;
        }
        if (bid == 0 && tid < NE) g_cnt[tid] = 0;   // safe: P4 done grid-wide
    }
}

// ---------------- launch ----------------
extern "C" void kernel_launch(void* const* d_in, const int* in_sizes, int n_in,
                              void* d_out, int out_size) {
    const long EX = (long)TOK*HID, EG = (long)NE*HID;
    const long EU = (long)NE*GUD*HID, ED = (long)NE*HID*IMD;

    const float *x = nullptr, *gw = nullptr, *wgu = nullptr, *wd = nullptr;
    for (int i = 0; i < n_in; i++) {
        long sz = in_sizes[i];
        if      (sz == EX && !x)   x   = (const float*)d_in[i];
        else if (sz == EG && !gw)  gw  = (const float*)d_in[i];
        else if (sz == EU && !wgu) wgu = (const float*)d_in[i];
        else if (sz == ED && !wd)  wd  = (const float*)d_in[i];
    }
    if (!x || !gw || !wgu || !wd) {
        if (n_in < 4) return;
        x = (const float*)d_in[0]; gw = (const float*)d_in[1];
        wgu = (const float*)d_in[2]; wd = (const float*)d_in[3];
    }
    cudaFuncSetAttribute(k_moe, cudaFuncAttributeMaxDynamicSharedMemorySize, SMEM_BYTES);
    k_moe<<<NBLK, NTH, SMEM_BYTES>>>(x, gw, wgu, wd, (float*)d_out);
}

// round 13
// speedup vs baseline: 2.6564x; 1.3056x over previous
#include <cuda_runtime.h>
#include <cuda_fp16.h>
#include <math.h>
#include <stdint.h>

#define TOK 1024
#define HID 2048
#define IMD 768
#define GUD 1536
#define NE  8
#define NBLK 148
#define NTH 512
#define NT (NBLK*NTH)

// ---- per-stage smem: Ah, Al (128x64 fp16) + Bh (128x64 fp16), 128B swizzled rows ----
#define SA_H 0
#define SA_L 16384
#define SB_H 32768
#define STAGE_BYTES 49152
#define NSTG 4
#define SMEM_BYTES (NSTG*STAGE_BYTES)   // 196608

// ---------------- scratch (device globals) ----------------
__device__ __align__(16) int   g_cnt[NE];     // zeroed at END of every launch
__device__ __align__(16) int   g_list[NE*TOK];
__device__ __align__(16) float g_topw[2*TOK];
__device__ __align__(16) float g_gu[2*TOK*GUD];
__device__ __align__(16) float g_o2[2*TOK*HID];
__device__ __align__(16) __half g_xh [TOK*HID],    g_xl [TOK*HID];
__device__ __align__(16) __half g_wuh[NE*GUD*HID];          // weights: hi only
__device__ __align__(16) __half g_wdh[NE*HID*IMD];
__device__ __align__(16) __half g_hbh[2*TOK*IMD],  g_hbl[2*TOK*IMD];
__device__ unsigned          g_bcnt   = 0;
__device__ volatile unsigned g_bsense = 0;

// ---------------- helpers ----------------
__device__ __forceinline__ uint32_t smem_u32(const void* p) {
    uint32_t a;
    asm("{ .reg .u64 t; cvta.to.shared.u64 t, %1; cvt.u32.u64 %0, t; }" : "=r"(a) : "l"(p));
    return a;
}
__device__ __forceinline__ void cp16(uint32_t dst, const void* src) {
    asm volatile("cp.async.cg.shared.global [%0], [%1], 16;" :: "r"(dst), "l"(src) : "memory");
}
__device__ __forceinline__ void cp16p(uint32_t dst, const void* src, int full) {
    asm volatile("cp.async.cg.shared.global [%0], [%1], 16, %2;"
                 :: "r"(dst), "l"(src), "r"(full ? 16 : 0) : "memory");
}
#define CP_COMMIT() asm volatile("cp.async.commit_group;" ::: "memory")
#define CP_WAIT(n)  asm volatile("cp.async.wait_group %0;" :: "n"(n) : "memory")

__device__ __forceinline__ void ldsm_x4(uint32_t r[4], uint32_t addr) {
    asm volatile("ldmatrix.sync.aligned.m8n8.x4.shared.b16 {%0,%1,%2,%3}, [%4];"
        : "=r"(r[0]), "=r"(r[1]), "=r"(r[2]), "=r"(r[3]) : "r"(addr));
}
__device__ __forceinline__ void mma_fp16(float c[4], const uint32_t a[4], const uint32_t b[2]) {
    asm volatile("mma.sync.aligned.m16n8k16.row.col.f32.f16.f16.f32 "
        "{%0,%1,%2,%3}, {%4,%5,%6,%7}, {%8,%9}, {%0,%1,%2,%3};"
        : "+f"(c[0]), "+f"(c[1]), "+f"(c[2]), "+f"(c[3])
        : "r"(a[0]), "r"(a[1]), "r"(a[2]), "r"(a[3]), "r"(b[0]), "r"(b[1]));
}
// fp32x4 -> fp16 hi + fp16 lo (lo = x - float(hi))
__device__ __forceinline__ void split4h(float4 v, uint2& hi, uint2& lo) {
    __half h0 = __float2half_rn(v.x), h1 = __float2half_rn(v.y);
    __half h2 = __float2half_rn(v.z), h3 = __float2half_rn(v.w);
    __half l0 = __float2half_rn(v.x - __half2float(h0));
    __half l1 = __float2half_rn(v.y - __half2float(h1));
    __half l2 = __float2half_rn(v.z - __half2float(h2));
    __half l3 = __float2half_rn(v.w - __half2float(h3));
    hi.x = (uint32_t)__half_as_ushort(h0) | ((uint32_t)__half_as_ushort(h1) << 16);
    hi.y = (uint32_t)__half_as_ushort(h2) | ((uint32_t)__half_as_ushort(h3) << 16);
    lo.x = (uint32_t)__half_as_ushort(l0) | ((uint32_t)__half_as_ushort(l1) << 16);
    lo.y = (uint32_t)__half_as_ushort(l2) | ((uint32_t)__half_as_ushort(l3) << 16);
}
// fp32x4 -> fp16x4 (hi only)
__device__ __forceinline__ uint2 cvt4h(float4 v) {
    uint2 r;
    r.x = (uint32_t)__half_as_ushort(__float2half_rn(v.x))
        | ((uint32_t)__half_as_ushort(__float2half_rn(v.y)) << 16);
    r.y = (uint32_t)__half_as_ushort(__float2half_rn(v.z))
        | ((uint32_t)__half_as_ushort(__float2half_rn(v.w)) << 16);
    return r;
}
__device__ __forceinline__ void gbar(unsigned& ls) {
    __syncthreads();
    if (threadIdx.x == 0) {
        unsigned target = ls + 1u;
        __threadfence();
        unsigned old = atomicAdd(&g_bcnt, 1u);
        if (old == NBLK - 1u) { g_bcnt = 0u; __threadfence(); g_bsense = target; }
        else { while (g_bsense != target) __nanosleep(128); }
        __threadfence();
    }
    ls += 1u;
    __syncthreads();
}
__device__ __forceinline__ float wsum(float v) {
#pragma unroll
    for (int o = 16; o; o >>= 1) v += __shfl_xor_sync(0xffffffffu, v, o);
    return v;
}

// ---- 128x128xK warp-MMA tile (16 warps of 32x32), 4-stage cp.async ----
// C = (Ah+Al) @ Bh^T : 2 fp16 terms, B quantization error ~1.4e-4 (OK vs 1e-3)
template<int KD, bool SECOND>
__device__ __forceinline__ void mma_tile(
    const __half* __restrict__ Ah, const __half* __restrict__ Al,
    const __half* __restrict__ Bh,
    int e, int m0, int n0, int ne, char* sm, uint32_t sb)
{
    const int tid = threadIdx.x;
    const int wid = tid >> 5, lane = tid & 31;

    // ---- global->smem mapping: thread = (row=tid>>2, 2 chunks of 16B per matrix) ----
    const int lrow = tid >> 2;
    const int cq   = (tid & 3) * 2;
    const int a_ok = (m0 + lrow < ne);
    const uint4 *agh, *agl;
    {
        int pair = a_ok ? g_list[e*TOK + m0 + lrow] : 0;
        size_t ar = (size_t)(SECOND ? pair : (pair >> 1)) * KD;
        agh = (const uint4*)(Ah + ar);
        agl = (const uint4*)(Al + ar);
    }
    const uint4* bgh = (const uint4*)(Bh + (size_t)(n0 + lrow) * KD);

    uint32_t sts[2];
#pragma unroll
    for (int j = 0; j < 2; j++) {
        int ch = cq + j;
        sts[j] = (uint32_t)(lrow * 128 + ((ch ^ (lrow & 7)) << 4));
    }

    const int KBN = KD / 64;
    auto issue = [&](int kb, int stg) {
        uint32_t base = sb + (uint32_t)stg * STAGE_BYTES;
#pragma unroll
        for (int j = 0; j < 2; j++) {
            int ch = cq + j;
            cp16p(base + SA_H + sts[j], agh + kb*8 + ch, a_ok);
            cp16p(base + SA_L + sts[j], agl + kb*8 + ch, a_ok);
            cp16 (base + SB_H + sts[j], bgh + kb*8 + ch);
        }
        CP_COMMIT();
    };

    // ---- warp tile: 32m x 32n, warp grid 4x4 ----
    const int wm = (wid & 3) * 32;
    const int wn = (wid >> 2) * 32;
    const int q  = lane >> 3, r8 = lane & 7;
    const int a_m_base = wm + (q & 1) * 8 + r8;
    const int a_ch_off = (q >> 1);
    const int b_n_base = wn + (q >> 1) * 8 + r8;
    const int b_ch_off = (q & 1);

    float acc[2][4][4];
#pragma unroll
    for (int i = 0; i < 2; i++)
#pragma unroll
        for (int j = 0; j < 4; j++)
#pragma unroll
            for (int c = 0; c < 4; c++) acc[i][j][c] = 0.f;

    issue(0, 0);
    if (KBN > 1) issue(1, 1);
    if (KBN > 2) issue(2, 2);

    for (int kb = 0; kb < KBN; kb++) {
        const int stg = kb % NSTG;
        const int rem = KBN - 1 - kb;
        if (rem >= 2)      { CP_WAIT(2); }
        else if (rem == 1) { CP_WAIT(1); }
        else               { CP_WAIT(0); }
        __syncthreads();
        if (kb + 3 < KBN) issue(kb + 3, (kb + 3) % NSTG);

        const uint32_t base = sb + (uint32_t)stg * STAGE_BYTES;
        const uint32_t saH = base + SA_H, saL = base + SA_L;
        const uint32_t sbH = base + SB_H;

#pragma unroll
        for (int ks = 0; ks < 4; ks++) {
            uint32_t ahf[2][4], alf[2][4], bhf[2][4];
#pragma unroll
            for (int mi = 0; mi < 2; mi++) {
                int m_ld = a_m_base + mi * 16;
                uint32_t off = (uint32_t)(m_ld * 128 + (((ks*2 + a_ch_off) ^ (m_ld & 7)) << 4));
                ldsm_x4(ahf[mi], saH + off);
                ldsm_x4(alf[mi], saL + off);
            }
#pragma unroll
            for (int nb = 0; nb < 2; nb++) {
                int n_ld = b_n_base + nb * 16;
                uint32_t off = (uint32_t)(n_ld * 128 + (((ks*2 + b_ch_off) ^ (n_ld & 7)) << 4));
                ldsm_x4(bhf[nb], sbH + off);
            }
            // term-major: hh across all 8 accs, then lh
#pragma unroll
            for (int mi = 0; mi < 2; mi++)
#pragma unroll
                for (int nb = 0; nb < 2; nb++)
#pragma unroll
                    for (int h = 0; h < 2; h++)
                        mma_fp16(acc[mi][nb*2 + h], ahf[mi], &bhf[nb][2*h]);
#pragma unroll
            for (int mi = 0; mi < 2; mi++)
#pragma unroll
                for (int nb = 0; nb < 2; nb++)
#pragma unroll
                    for (int h = 0; h < 2; h++)
                        mma_fp16(acc[mi][nb*2 + h], alf[mi], &bhf[nb][2*h]);
        }
    }

    // ---- epilogue ----
    const int g  = lane >> 2, t4 = lane & 3;
#pragma unroll
    for (int mi = 0; mi < 2; mi++) {
        int mr0 = m0 + wm + mi*16 + g;
        int mr1 = mr0 + 8;
        float* row0 = nullptr; float* row1 = nullptr;
        if (mr0 < ne) {
            int p = g_list[e*TOK + mr0];
            row0 = SECOND ? (g_o2 + (size_t)p * HID) : (g_gu + (size_t)p * GUD);
        }
        if (mr1 < ne) {
            int p = g_list[e*TOK + mr1];
            row1 = SECOND ? (g_o2 + (size_t)p * HID) : (g_gu + (size_t)p * GUD);
        }
#pragma unroll
        for (int nj = 0; nj < 4; nj++) {
            int n = n0 + wn + nj*8 + t4*2;
            if (row0) *(float2*)(row0 + n) = make_float2(acc[mi][nj][0], acc[mi][nj][1]);
            if (row1) *(float2*)(row1 + n) = make_float2(acc[mi][nj][2], acc[mi][nj][3]);
        }
    }
    __syncthreads();
}

// ---------------- persistent fused MoE kernel ----------------
__global__ void __launch_bounds__(NTH) k_moe(
    const float* __restrict__ x,   const float* __restrict__ gw,
    const float* __restrict__ wgu, const float* __restrict__ wd,
    float* __restrict__ out)
{
    extern __shared__ char sm[];
    const uint32_t sb = smem_u32(sm);
    const int tid  = threadIdx.x;
    const int wid  = tid >> 5;
    const int lane = tid & 31;
    const int bid  = blockIdx.x;
    const int gtid = bid * NTH + tid;
    unsigned ls = g_bsense;

    // ---- P0: router + convert inputs/weights (g_cnt arrives zeroed) ----
    {
        int t = bid * 16 + wid;
        if (t < TOK) {
            const float* xr = x + (size_t)t * HID;
            float acc[NE];
#pragma unroll
            for (int e2 = 0; e2 < NE; e2++) acc[e2] = 0.f;
            for (int j = lane; j < HID; j += 32) {
                float xv = xr[j];
#pragma unroll
                for (int e2 = 0; e2 < NE; e2++) acc[e2] += xv * gw[e2*HID + j];
            }
#pragma unroll
            for (int e2 = 0; e2 < NE; e2++) acc[e2] = wsum(acc[e2]);
            if (lane == 0) {
                int i1 = 0; float v1 = acc[0];
#pragma unroll
                for (int e2 = 1; e2 < NE; e2++) if (acc[e2] > v1) { v1 = acc[e2]; i1 = e2; }
                int i2 = (i1 == 0) ? 1 : 0; float v2 = acc[i2];
#pragma unroll
                for (int e2 = 0; e2 < NE; e2++) if (e2 != i1 && acc[e2] > v2) { v2 = acc[e2]; i2 = e2; }
                float r  = expf(v2 - v1);          // full-E softmax + top-2 renorm
                float w1 = 1.f / (1.f + r);        // == 2-way softmax over {v1,v2}
                g_topw[2*t+0] = w1;
                g_topw[2*t+1] = r * w1;
                int p1 = atomicAdd(&g_cnt[i1], 1); g_list[i1*TOK + p1] = 2*t + 0;
                int p2 = atomicAdd(&g_cnt[i2], 1); g_list[i2*TOK + p2] = 2*t + 1;
            }
        }
        uint2 hi, lo;
        for (long i = gtid; i < (long)TOK*HID/4; i += NT) {
            split4h(((const float4*)x)[i], hi, lo);
            ((uint2*)g_xh)[i] = hi; ((uint2*)g_xl)[i] = lo;
        }
        for (long i = gtid; i < (long)NE*GUD*HID/4; i += NT)
            ((uint2*)g_wuh)[i] = cvt4h(((const float4*)wgu)[i]);
        for (long i = gtid; i < (long)NE*HID*IMD/4; i += NT)
            ((uint2*)g_wdh)[i] = cvt4h(((const float4*)wd)[i]);
    }
    gbar(ls);

    // ---- build compact m-tile table (redundantly per CTA) ----
    int cnt[NE], cmt[NE+1];
    cmt[0] = 0;
#pragma unroll
    for (int e2 = 0; e2 < NE; e2++) {
        cnt[e2] = g_cnt[e2];
        cmt[e2+1] = cmt[e2] + ((cnt[e2] + 127) >> 7);
    }
    const int total_mt = cmt[NE];

    // ---- P2: GEMM1  x @ Wgu^T -> g_gu  (dense job list: total_mt x 12) ----
    for (int job = bid; job < total_mt * 12; job += NBLK) {
        int jm = job / 12, nt = job % 12;
        int e = 0;
#pragma unroll
        for (int e2 = 0; e2 < NE; e2++) if (jm >= cmt[e2+1]) e = e2 + 1;
        int mt = jm - cmt[e];
        mma_tile<HID, false>(g_xh, g_xl, g_wuh + (size_t)e*GUD*HID,
                             e, mt*128, nt*128, cnt[e], sm, sb);
    }
    gbar(ls);

    // ---- P3: act h = silu(g)*u -> fp16 hi/lo ----
    {
        const int n4 = 2*TOK*IMD/4;
        for (int i = gtid; i < n4; i += NT) {
            int p  = i / (IMD/4);
            int j4 = i - p * (IMD/4);
            float4 g4 = *(const float4*)(g_gu + (size_t)p*GUD + 4*j4);
            float4 u4 = *(const float4*)(g_gu + (size_t)p*GUD + IMD + 4*j4);
            float4 h4;
            h4.x = (g4.x / (1.f + expf(-g4.x))) * u4.x;
            h4.y = (g4.y / (1.f + expf(-g4.y))) * u4.y;
            h4.z = (g4.z / (1.f + expf(-g4.z))) * u4.z;
            h4.w = (g4.w / (1.f + expf(-g4.w))) * u4.w;
            uint2 hi, lo;
            split4h(h4, hi, lo);
            ((uint2*)g_hbh)[i] = hi; ((uint2*)g_hbl)[i] = lo;
        }
    }
    gbar(ls);

    // ---- P4: GEMM2  h @ Wd^T -> g_o2  (dense job list: total_mt x 16) ----
    for (int job = bid; job < total_mt * 16; job += NBLK) {
        int jm = job / 16, nt = job % 16;
        int e = 0;
#pragma unroll
        for (int e2 = 0; e2 < NE; e2++) if (jm >= cmt[e2+1]) e = e2 + 1;
        int mt = jm - cmt[e];
        mma_tile<IMD, true>(g_hbh, g_hbl, g_wdh + (size_t)e*HID*IMD,
                            e, mt*128, nt*128, cnt[e], sm, sb);
    }
    gbar(ls);

    // ---- P5: combine out[t] = w1*y[2t] + w2*y[2t+1]; reset g_cnt ----
    {
        const int n4 = TOK*HID/4;
        for (int i = gtid; i < n4; i += NT) {
            int t  = i / (HID/4);
            int j4 = i - t * (HID/4);
            float w1 = g_topw[2*t+0], w2 = g_topw[2*t+1];
            float4 y1 = ((const float4*)g_o2)[(size_t)(2*t  )*(HID/4) + j4];
            float4 y2 = ((const float4*)g_o2)[(size_t)(2*t+1)*(HID/4) + j4];
            float4 o;
            o.x = w1*y1.x + w2*y2.x;
            o.y = w1*y1.y + w2*y2.y;
            o.z = w1*y1.z + w2*y2.z;
            o.w = w1*y1.w + w2*y2.w;
            ((float4*)out)[i] = o;
        }
        if (bid == 0 && tid < NE) g_cnt[tid] = 0;   // safe: P4 done grid-wide
    }
}

// ---------------- launch ----------------
extern "C" void kernel_launch(void* const* d_in, const int* in_sizes, int n_in,
                              void* d_out, int out_size) {
    const long EX = (long)TOK*HID, EG = (long)NE*HID;
    const long EU = (long)NE*GUD*HID, ED = (long)NE*HID*IMD;

    const float *x = nullptr, *gw = nullptr, *wgu = nullptr, *wd = nullptr;
    for (int i = 0; i < n_in; i++) {
        long sz = in_sizes[i];
        if      (sz == EX && !x)   x   = (const float*)d_in[i];
        else if (sz == EG && !gw)  gw  = (const float*)d_in[i];
        else if (sz == EU && !wgu) wgu = (const float*)d_in[i];
        else if (sz == ED && !wd)  wd  = (const float*)d_in[i];
    }
    if (!x || !gw || !wgu || !wd) {
        if (n_in < 4) return;
        x = (const float*)d_in[0]; gw = (const float*)d_in[1];
        wgu = (const float*)d_in[2]; wd = (const float*)d_in[3];
    }
    cudaFuncSetAttribute(k_moe, cudaFuncAttributeMaxDynamicSharedMemorySize, SMEM_BYTES);
    k_moe<<<NBLK, NTH, SMEM_BYTES>>>(x, gw, wgu, wd, (float*)d_out);
}